// round 6
// baseline (speedup 1.0000x reference)
#include <cuda_runtime.h>

// LatentLinearModel: r[i] = dot(U[users[i]], V[jokes[i]]) + a[users[i]] + b[jokes[i]] + g
// B = 1048576, K = 64.
//
// Round 6: rotating two-stage cp.async pipeline, same 32KB smem as R4.
// R4 was bursty (issue 32KB -> wait_group 0 -> compute with NOTHING in
// flight). Here each block alternates two 16KB stage buffers: wait_group 1
// leaves the newer tile's gathers in flight while the older tile is computed,
// and the freed buffer is refilled immediately. Biases ride the same cp.async
// groups (4B copies), so compute never touches global memory.

#define TPR    16                   // threads per row
#define RPG    2                    // rows per 16-lane group per stage
#define BLOCK  256
#define GROUPS (BLOCK / TPR)        // 16
#define TROWS  (GROUPS * RPG)       // 32 rows per tile/stage
#define BLOCKS_PER_SM 6

__device__ __forceinline__ void cp_async16(void* smem, const void* gmem) {
    unsigned s = (unsigned)__cvta_generic_to_shared(smem);
    asm volatile("cp.async.cg.shared.global [%0], [%1], 16;" :: "r"(s), "l"(gmem));
}
__device__ __forceinline__ void cp_async4(void* smem, const void* gmem) {
    unsigned s = (unsigned)__cvta_generic_to_shared(smem);
    asm volatile("cp.async.ca.shared.global [%0], [%1], 4;" :: "r"(s), "l"(gmem));
}

__global__ void __launch_bounds__(BLOCK)
latent_linear_kernel(const int* __restrict__ users,
                     const int* __restrict__ jokes,
                     const float4* __restrict__ U4,
                     const float4* __restrict__ V4,
                     const float* __restrict__ a,
                     const float* __restrict__ b,
                     const float* __restrict__ g,
                     float* __restrict__ out,
                     int B, int num_tiles) {
    __shared__ float4 sU[2][TROWS][TPR];   // 2 x 8 KB
    __shared__ float4 sV[2][TROWS][TPR];   // 2 x 8 KB
    __shared__ float  sA[2][TROWS];
    __shared__ float  sB[2][TROWS];

    const int lane = threadIdx.x & (TPR - 1);
    const int lr0  = (threadIdx.x >> 4) * RPG;   // this group's local row base
    const int stride = gridDim.x;

    const float gg = __ldg(&g[0]);

    const int t0 = blockIdx.x;
    if (t0 >= num_tiles) return;

    // ---- index loader (int2: RPG=2 consecutive rows, 8B aligned) ----
    auto load_idx = [&](int t) -> int4 {
        int row0 = t * TROWS + lr0;
        if (row0 + 1 >= B) row0 = B - 2;         // clamp (B divisible in practice)
        int2 u = __ldg((const int2*)(users + row0));
        int2 j = __ldg((const int2*)(jokes + row0));
        return make_int4(u.x, u.y, j.x, j.y);
    };
    // ---- issue one tile's gathers + biases into stage p, commit as a group ----
    auto issue = [&](int p, int4 idx) {
        cp_async16(&sU[p][lr0 + 0][lane], &U4[(size_t)idx.x * 16 + lane]);
        cp_async16(&sU[p][lr0 + 1][lane], &U4[(size_t)idx.y * 16 + lane]);
        cp_async16(&sV[p][lr0 + 0][lane], &V4[(size_t)idx.z * 16 + lane]);
        cp_async16(&sV[p][lr0 + 1][lane], &V4[(size_t)idx.w * 16 + lane]);
        if (lane == 0) {
            cp_async4(&sA[p][lr0 + 0], &a[idx.x]);
            cp_async4(&sA[p][lr0 + 1], &a[idx.y]);
            cp_async4(&sB[p][lr0 + 0], &b[idx.z]);
            cp_async4(&sB[p][lr0 + 1], &b[idx.w]);
        }
        asm volatile("cp.async.commit_group;");
    };

    // ---- pipeline warm-up: stages for t0 and t0+stride ----
    issue(0, load_idx(t0));
    const int t1 = t0 + stride;
    if (t1 < num_tiles) issue(1, load_idx(t1));

    int4 pf;                                     // idx for tile t+2*stride
    int tpf = t0 + 2 * stride;
    if (tpf < num_tiles) pf = load_idx(tpf);

    int k = 0;
    for (int t = t0; t < num_tiles; t += stride, k++) {
        const int p = k & 1;

        if (t + stride < num_tiles) {
            asm volatile("cp.async.wait_group 1;" ::: "memory");  // oldest done, newer in flight
        } else {
            asm volatile("cp.async.wait_group 0;" ::: "memory");  // tail
        }

        // ---- compute tile t from stage p (each thread reads only its own slots) ----
        const int row0 = t * TROWS + lr0;
#pragma unroll
        for (int r = 0; r < RPG; r++) {
            float4 uu = sU[p][lr0 + r][lane];
            float4 vv = sV[p][lr0 + r][lane];
            float d = fmaf(uu.x, vv.x, fmaf(uu.y, vv.y, fmaf(uu.z, vv.z, uu.w * vv.w)));
            d += __shfl_xor_sync(0xffffffffu, d, 8);
            d += __shfl_xor_sync(0xffffffffu, d, 4);
            d += __shfl_xor_sync(0xffffffffu, d, 2);
            d += __shfl_xor_sync(0xffffffffu, d, 1);
            if (lane == 0) {
                int row = row0 + r;
                if (row < B) out[row] = d + sA[p][lr0 + r] + sB[p][lr0 + r] + gg;
            }
        }

        // ---- refill freed stage p with tile t+2*stride; prefetch next idx ----
        const int tn = t + 2 * stride;
        if (tn < num_tiles) {
            issue(p, pf);
            const int tn3 = tn + stride;
            if (tn3 < num_tiles) pf = load_idx(tn3);
        }
        // No __syncthreads anywhere: smem slots are strictly thread-private,
        // and per-thread same-address ordering covers the LDS -> cp.async reuse.
    }
}

extern "C" void kernel_launch(void* const* d_in, const int* in_sizes, int n_in,
                              void* d_out, int out_size) {
    // metadata order: users, jokes, U, V, a, b, g
    const int*    users = (const int*)d_in[0];
    const int*    jokes = (const int*)d_in[1];
    const float4* U4    = (const float4*)d_in[2];
    const float4* V4    = (const float4*)d_in[3];
    const float*  a     = (const float*)d_in[4];
    const float*  b     = (const float*)d_in[5];
    const float*  g     = (const float*)d_in[6];
    float* out = (float*)d_out;

    int B = in_sizes[0];
    int num_tiles = (B + TROWS - 1) / TROWS;

    int sms = 148;
    cudaDeviceGetAttribute(&sms, cudaDevAttrMultiProcessorCount, 0);

    int grid = sms * BLOCKS_PER_SM;
    if (grid > num_tiles) grid = num_tiles;

    latent_linear_kernel<<<grid, BLOCK>>>(users, jokes, U4, V4, a, b, g, out,
                                          B, num_tiles);
}